// round 10
// baseline (speedup 1.0000x reference)
#include <cuda_runtime.h>
#include <cuda_bf16.h>
#include <math_constants.h>

// GeomAttention: B=2, L=S=2048, H=8, E=D=32, fp32.
// Cauchy-Schwarz => relu never fires: score = c*(dot+dot^2) - c*qn2*kn2.
// Shift softmax (log2 domain): C2 = min(c2*qn2*KMIN, 100) is a safe fixed shift.
//
// R10: 128-thread blocks (4 warps -> all 4 SMSPs; 64-thread blocks stranded
// half the SM per wid%4 mapping). S-split moved INSIDE the block: warps 0-1
// do S[0:1024), warps 2-3 do S[1024:2048) for the same 128 rows; merge via
// smem (no global partials, no atomics). 2 rows/thread, chunk-8 scoring,
// packed fma.rn.f32x2, ex2.approx with folded log2e.

static constexpr int B_ = 2, L_ = 2048, H_ = 8, E_ = 32;
static constexpr int TS = 64;                // keys per SMEM tile (per half)
static constexpr int CH = 8;                 // keys per score chunk
static constexpr int THREADS = 128;          // 4 warps
static constexpr int HALFT = 64;             // threads per S-half
static constexpr int SKEYS = L_ / 2;         // 1024 keys per half
static constexpr int ROWSPB = 128;           // rows per block (2 per thread)

__device__ float g_kmin[B_ * H_];
__device__ float g_kn2[B_ * H_ * L_];        // [(b*H+h)*L + s]

typedef unsigned long long u64;

__device__ __forceinline__ u64 pk2(float a, float b) {
    u64 r; asm("mov.b64 %0, {%1,%2};" : "=l"(r) : "f"(a), "f"(b)); return r;
}
__device__ __forceinline__ float2 upk2(u64 v) {
    float2 r; asm("mov.b64 {%0,%1}, %2;" : "=f"(r.x), "=f"(r.y) : "l"(v)); return r;
}
__device__ __forceinline__ u64 ffma2(u64 a, u64 b, u64 c) {
    u64 d; asm("fma.rn.f32x2 %0, %1, %2, %3;" : "=l"(d) : "l"(a), "l"(b), "l"(c)); return d;
}
__device__ __forceinline__ float ex2f(float x) {
    float r; asm("ex2.approx.f32 %0, %1;" : "=f"(r) : "f"(x)); return r;
}

// ---- pre-kernel: per-key |k|^2 and per-(b,h) min ----
__global__ __launch_bounds__(256) void kprep_kernel(const float* __restrict__ K)
{
    const int bh = blockIdx.x;               // 0..B*H-1
    const int b = bh / H_, h = bh % H_;
    const float* kbase = K + (((size_t)b * L_) * H_ + h) * E_;
    float mn = CUDART_INF_F;
    for (int s = threadIdx.x; s < L_; s += 256) {
        const float4* kp = (const float4*)(kbase + (size_t)s * (H_ * E_));
        float kn = 0.f;
        #pragma unroll
        for (int j = 0; j < 8; j++) {
            float4 v = kp[j];
            kn += v.x*v.x + v.y*v.y + v.z*v.z + v.w*v.w;
        }
        g_kn2[(size_t)bh * L_ + s] = kn;
        mn = fminf(mn, kn);
    }
    #pragma unroll
    for (int o = 16; o; o >>= 1) mn = fminf(mn, __shfl_xor_sync(0xffffffffu, mn, o));
    __shared__ float red[8];
    if ((threadIdx.x & 31) == 0) red[threadIdx.x >> 5] = mn;
    __syncthreads();
    if (threadIdx.x == 0) {
        float r = red[0];
        #pragma unroll
        for (int w = 1; w < 8; w++) r = fminf(r, red[w]);
        g_kmin[bh] = r;
    }
}

__global__ __launch_bounds__(THREADS, 2) void geom_attn_fused(
    const float* __restrict__ Q, const float* __restrict__ K,
    const float* __restrict__ V, float* __restrict__ O)
{
    __shared__ float4 sK[2][TS * 8];   // 2 x 8 KB (also reused as merge buffer)
    __shared__ float4 sV[2][TS * 8];   // 2 x 8 KB
    __shared__ float  sKn2[2][TS];     // 512 B (also reused for ls merge)

    const int tid = threadIdx.x;
    const int sid = tid >> 6;          // which S-half this thread works on
    const int t   = tid & 63;
    const int h   = blockIdx.y;
    const int b   = blockIdx.z;
    const int lbase = blockIdx.x * ROWSPB;
    const int l0  = lbase + t;
    const int l1  = l0 + HALFT;
    const int bh  = b * H_ + h;

    // ---- load 2 query rows; |q|^2 each ----
    const float* qp0 = Q + (((size_t)b * L_ + l0) * H_ + h) * E_;
    const float* qp1 = Q + (((size_t)b * L_ + l1) * H_ + h) * E_;
    u64 qa[16], qb[16];
    float qn2a = 0.f, qn2b = 0.f;
    #pragma unroll
    for (int j = 0; j < 8; j++) {
        float4 tt = ((const float4*)qp0)[j];
        qa[2*j] = pk2(tt.x, tt.y); qa[2*j+1] = pk2(tt.z, tt.w);
        qn2a += tt.x*tt.x + tt.y*tt.y + tt.z*tt.z + tt.w*tt.w;
        float4 uu = ((const float4*)qp1)[j];
        qb[2*j] = pk2(uu.x, uu.y); qb[2*j+1] = pk2(uu.z, uu.w);
        qn2b += uu.x*uu.x + uu.y*uu.y + uu.z*uu.z + uu.w*uu.w;
    }

    // log2-domain constants: p = 2^(c2*(dot+dot^2) - c2*qn2*kn2 + C2)
    const float c2  = 0.5f * rsqrtf((float)E_) * 1.4426950408889634f;
    const float cqa = c2 * qn2a, cqb = c2 * qn2b;
    const float km  = g_kmin[bh];
    const float Ca  = fminf(cqa * km, 100.f);   // safe fixed shift (log2)
    const float Cb  = fminf(cqb * km, 100.f);

    float ls0 = 0.f, ls1 = 0.f;
    u64 acca[16], accb[16];
    #pragma unroll
    for (int j = 0; j < 16; j++) { acca[j] = 0ull; accb[j] = 0ull; }

    const int key0 = sid * SKEYS;
    const float* kbase = K + (((size_t)b * L_) * H_ + h) * E_;
    const float* vbase = V + (((size_t)b * L_) * H_ + h) * E_;
    const float* knb   = &g_kn2[(size_t)bh * L_ + key0];

    for (int s0 = 0; s0 < SKEYS; s0 += TS) {
        // each half loads its own tile (64 threads, 8 float4 rows each)
        #pragma unroll
        for (int i = t; i < TS * 8; i += HALFT) {
            int r = i >> 3, j = i & 7;
            size_t off = (size_t)(key0 + s0 + r) * (H_ * E_);
            sK[sid][i] = ((const float4*)(kbase + off))[j];
            sV[sid][i] = ((const float4*)(vbase + off))[j];
        }
        sKn2[sid][t] = knb[s0 + t];
        __syncthreads();

        for (int c0 = 0; c0 < TS; c0 += CH) {
            float sa[CH], sb[CH];
            // ---- phase 1: scores for CH keys x 2 rows ----
            #pragma unroll
            for (int u = 0; u < CH; u++) {
                const ulonglong2* kp = (const ulonglong2*)&sK[sid][(c0 + u) * 8];
                u64 a0 = 0ull, a1 = 0ull, b0 = 0ull, b1 = 0ull;
                #pragma unroll
                for (int j = 0; j < 8; j++) {
                    ulonglong2 kk = kp[j];          // broadcast across warp
                    a0 = ffma2(qa[2*j],   kk.x, a0);
                    a1 = ffma2(qa[2*j+1], kk.y, a1);
                    b0 = ffma2(qb[2*j],   kk.x, b0);
                    b1 = ffma2(qb[2*j+1], kk.y, b1);
                }
                float2 ra0 = upk2(a0), ra1 = upk2(a1);
                float2 rb0 = upk2(b0), rb1 = upk2(b1);
                float dota = (ra0.x + ra0.y) + (ra1.x + ra1.y);
                float dotb = (rb0.x + rb0.y) + (rb1.x + rb1.y);
                float kn2  = sKn2[sid][c0 + u];
                float ta = fmaf(dota, dota, dota);   // dot + dot^2
                float tb = fmaf(dotb, dotb, dotb);
                sa[u] = fmaf(c2, ta, fmaf(-cqa, kn2, Ca));
                sb[u] = fmaf(c2, tb, fmaf(-cqb, kn2, Cb));
            }
            // ---- phase 2: exp2 + PV accumulate (straight-line) ----
            #pragma unroll
            for (int u = 0; u < CH; u++) {
                float pa = ex2f(sa[u]);
                float pb = ex2f(sb[u]);
                ls0 += pa; ls1 += pb;
                u64 ppa = pk2(pa, pa), ppb = pk2(pb, pb);
                const ulonglong2* vp = (const ulonglong2*)&sV[sid][(c0 + u) * 8];
                #pragma unroll
                for (int j = 0; j < 8; j++) {
                    ulonglong2 vv = vp[j];
                    acca[2*j]   = ffma2(ppa, vv.x, acca[2*j]);
                    acca[2*j+1] = ffma2(ppa, vv.y, acca[2*j+1]);
                    accb[2*j]   = ffma2(ppb, vv.x, accb[2*j]);
                    accb[2*j+1] = ffma2(ppb, vv.y, accb[2*j+1]);
                }
            }
        }
        __syncthreads();
    }

    // ---- in-block merge of the two S-halves via smem ----
    // Layout [j][t] (stride 16B across threads) -> conflict-free.
    float4* mA  = &sK[0][0];           // 8 KB: row-l0 accs from half 1
    float4* mB  = &sK[1][0];           // 8 KB: row-l1 accs from half 1
    float*  lsb = &sKn2[0][0];         // 128 floats: ls from half 1

    if (sid == 1) {
        #pragma unroll
        for (int j = 0; j < 8; j++) {
            float2 x = upk2(acca[2*j]), y = upk2(acca[2*j+1]);
            mA[j * HALFT + t] = make_float4(x.x, x.y, y.x, y.y);
            float2 u = upk2(accb[2*j]), v = upk2(accb[2*j+1]);
            mB[j * HALFT + t] = make_float4(u.x, u.y, v.x, v.y);
        }
        lsb[t] = ls0; lsb[HALFT + t] = ls1;
    }
    __syncthreads();
    if (sid == 0) {
        const float inv0 = 1.0f / (ls0 + lsb[t]);
        const float inv1 = 1.0f / (ls1 + lsb[HALFT + t]);
        float* op0 = O + (((size_t)b * L_ + l0) * H_ + h) * E_;
        float* op1 = O + (((size_t)b * L_ + l1) * H_ + h) * E_;
        #pragma unroll
        for (int j = 0; j < 8; j++) {
            float2 x = upk2(acca[2*j]), y = upk2(acca[2*j+1]);
            float4 m = mA[j * HALFT + t];
            ((float4*)op0)[j] = make_float4((x.x + m.x) * inv0, (x.y + m.y) * inv0,
                                            (y.x + m.z) * inv0, (y.y + m.w) * inv0);
            float2 u = upk2(accb[2*j]), v = upk2(accb[2*j+1]);
            float4 n = mB[j * HALFT + t];
            ((float4*)op1)[j] = make_float4((u.x + n.x) * inv1, (u.y + n.y) * inv1,
                                            (v.x + n.z) * inv1, (v.y + n.w) * inv1);
        }
    }
}

extern "C" void kernel_launch(void* const* d_in, const int* in_sizes, int n_in,
                              void* d_out, int out_size) {
    const float* Q = (const float*)d_in[0];
    const float* K = (const float*)d_in[1];
    const float* V = (const float*)d_in[2];
    float* O = (float*)d_out;
    (void)in_sizes; (void)n_in; (void)out_size;
    kprep_kernel<<<B_ * H_, 256>>>(K);
    dim3 grid(L_ / ROWSPB, H_, B_);            // 16 x 8 x 2 = 256 blocks
    geom_attn_fused<<<grid, THREADS>>>(Q, K, V, O);
}

// round 11
// speedup vs baseline: 1.0175x; 1.0175x over previous
#include <cuda_runtime.h>
#include <cuda_bf16.h>
#include <math_constants.h>

// GeomAttention: B=2, L=S=2048, H=8, E=D=32, fp32.
// Cauchy-Schwarz => relu never fires: score = c*(dot+dot^2) - c*qn2*kn2.
// Shift softmax (log2): C2 = min(c2*qn2*KMIN, 100), p = 2^(score2 + C2).
//
// R11: R9's algorithm with 1-warp blocks (no inter-warp barriers; 8 blocks/SM
// -> ~7 warps/SM in one wave), log2-domain ex2, packed add.rn.f32x2 dot
// reduction. 2 rows/thread, chunk-8 two-phase scoring, SPLITS=2, fused
// last-block merge, packed fma.rn.f32x2.

static constexpr int B_ = 2, L_ = 2048, H_ = 8, E_ = 32;
static constexpr int SPLITS = 2;
static constexpr int SKEYS  = L_ / SPLITS;   // 1024
static constexpr int TS = 64;                // keys per SMEM tile
static constexpr int CH = 8;                 // keys per score chunk
static constexpr int THREADS = 32;           // 1 warp
static constexpr int ROWSPB = 2 * THREADS;   // 64 rows per block
static constexpr int NR = B_ * L_ * H_;      // 32768 rows
static constexpr int NGROUPS = (L_ / ROWSPB) * H_ * B_;  // 512

__device__ float  g_l[SPLITS * NR];
__device__ float4 g_acc[SPLITS * NR * 8];
__device__ float  g_kmin[B_ * H_];
__device__ float  g_kn2[B_ * H_ * L_];       // [(b*H+h)*L + s]
__device__ int    g_cnt[NGROUPS];            // zero-init; self-resetting

typedef unsigned long long u64;

__device__ __forceinline__ u64 pk2(float a, float b) {
    u64 r; asm("mov.b64 %0, {%1,%2};" : "=l"(r) : "f"(a), "f"(b)); return r;
}
__device__ __forceinline__ float2 upk2(u64 v) {
    float2 r; asm("mov.b64 {%0,%1}, %2;" : "=f"(r.x), "=f"(r.y) : "l"(v)); return r;
}
__device__ __forceinline__ u64 ffma2(u64 a, u64 b, u64 c) {
    u64 d; asm("fma.rn.f32x2 %0, %1, %2, %3;" : "=l"(d) : "l"(a), "l"(b), "l"(c)); return d;
}
__device__ __forceinline__ u64 fadd2(u64 a, u64 b) {
    u64 d; asm("add.rn.f32x2 %0, %1, %2;" : "=l"(d) : "l"(a), "l"(b)); return d;
}
__device__ __forceinline__ float ex2f(float x) {
    float r; asm("ex2.approx.f32 %0, %1;" : "=f"(r) : "f"(x)); return r;
}

// ---- pre-kernel: per-key |k|^2 and per-(b,h) min ----
__global__ __launch_bounds__(256) void kprep_kernel(const float* __restrict__ K)
{
    const int bh = blockIdx.x;               // 0..B*H-1
    const int b = bh / H_, h = bh % H_;
    const float* kbase = K + (((size_t)b * L_) * H_ + h) * E_;
    float mn = CUDART_INF_F;
    for (int s = threadIdx.x; s < L_; s += 256) {
        const float4* kp = (const float4*)(kbase + (size_t)s * (H_ * E_));
        float kn = 0.f;
        #pragma unroll
        for (int j = 0; j < 8; j++) {
            float4 v = kp[j];
            kn += v.x*v.x + v.y*v.y + v.z*v.z + v.w*v.w;
        }
        g_kn2[(size_t)bh * L_ + s] = kn;
        mn = fminf(mn, kn);
    }
    #pragma unroll
    for (int o = 16; o; o >>= 1) mn = fminf(mn, __shfl_xor_sync(0xffffffffu, mn, o));
    __shared__ float red[8];
    if ((threadIdx.x & 31) == 0) red[threadIdx.x >> 5] = mn;
    __syncthreads();
    if (threadIdx.x == 0) {
        float r = red[0];
        #pragma unroll
        for (int w = 1; w < 8; w++) r = fminf(r, red[w]);
        g_kmin[bh] = r;
    }
}

__global__ __launch_bounds__(THREADS, 8) void geom_attn_fused(
    const float* __restrict__ Q, const float* __restrict__ K,
    const float* __restrict__ V, float* __restrict__ O)
{
    __shared__ float4 sK[TS * 8];    // 8 KB
    __shared__ float4 sV[TS * 8];    // 8 KB
    __shared__ float  sKn2[TS];

    const int tid   = threadIdx.x;
    const int h     = blockIdx.y;
    const int bz    = blockIdx.z;
    const int b     = bz >> 1;                 // SPLITS == 2
    const int split = bz & 1;
    const int lbase = blockIdx.x * ROWSPB;
    const int l0    = lbase + tid;
    const int l1    = l0 + THREADS;
    const int bh    = b * H_ + h;

    // ---- load 2 query rows; |q|^2 each ----
    const float* qp0 = Q + (((size_t)b * L_ + l0) * H_ + h) * E_;
    const float* qp1 = Q + (((size_t)b * L_ + l1) * H_ + h) * E_;
    u64 qa[16], qb[16];
    float qn2a = 0.f, qn2b = 0.f;
    #pragma unroll
    for (int j = 0; j < 8; j++) {
        float4 t = ((const float4*)qp0)[j];
        qa[2*j] = pk2(t.x, t.y); qa[2*j+1] = pk2(t.z, t.w);
        qn2a += t.x*t.x + t.y*t.y + t.z*t.z + t.w*t.w;
        float4 u = ((const float4*)qp1)[j];
        qb[2*j] = pk2(u.x, u.y); qb[2*j+1] = pk2(u.z, u.w);
        qn2b += u.x*u.x + u.y*u.y + u.z*u.z + u.w*u.w;
    }

    // log2-domain: p = 2^(c2*(dot+dot^2) - c2*qn2*kn2 + C2)
    const float c2  = 0.5f * rsqrtf((float)E_) * 1.4426950408889634f;
    const float cqa = c2 * qn2a, cqb = c2 * qn2b;
    const float km  = g_kmin[bh];
    const float Ca  = fminf(cqa * km, 100.f);  // safe fixed shift (log2)
    const float Cb  = fminf(cqb * km, 100.f);

    float ls0 = 0.f, ls1 = 0.f;
    u64 acca[16], accb[16];
    #pragma unroll
    for (int j = 0; j < 16; j++) { acca[j] = 0ull; accb[j] = 0ull; }

    const int key0 = split * SKEYS;
    const float* kbase = K + (((size_t)b * L_) * H_ + h) * E_;
    const float* vbase = V + (((size_t)b * L_) * H_ + h) * E_;
    const float* knb   = &g_kn2[(size_t)bh * L_ + key0];

    for (int s0 = 0; s0 < SKEYS; s0 += TS) {
        #pragma unroll
        for (int i = tid; i < TS * 8; i += THREADS) {
            int r = i >> 3, j = i & 7;
            size_t off = (size_t)(key0 + s0 + r) * (H_ * E_);
            sK[i] = ((const float4*)(kbase + off))[j];
            sV[i] = ((const float4*)(vbase + off))[j];
        }
        #pragma unroll
        for (int i = tid; i < TS; i += THREADS)
            sKn2[i] = knb[s0 + i];
        __syncwarp();

        for (int c0 = 0; c0 < TS; c0 += CH) {
            float sa[CH], sb[CH];
            // ---- phase 1: scores for CH keys x 2 rows ----
            #pragma unroll
            for (int u = 0; u < CH; u++) {
                const ulonglong2* kp = (const ulonglong2*)&sK[(c0 + u) * 8];
                u64 a0 = 0ull, a1 = 0ull, b0 = 0ull, b1 = 0ull;
                #pragma unroll
                for (int j = 0; j < 8; j++) {
                    ulonglong2 kk = kp[j];          // broadcast across warp
                    a0 = ffma2(qa[2*j],   kk.x, a0);
                    a1 = ffma2(qa[2*j+1], kk.y, a1);
                    b0 = ffma2(qb[2*j],   kk.x, b0);
                    b1 = ffma2(qb[2*j+1], kk.y, b1);
                }
                float2 ra = upk2(fadd2(a0, a1));
                float2 rb = upk2(fadd2(b0, b1));
                float dota = ra.x + ra.y;
                float dotb = rb.x + rb.y;
                float kn2  = sKn2[c0 + u];
                float ta = fmaf(dota, dota, dota);   // dot + dot^2
                float tb = fmaf(dotb, dotb, dotb);
                sa[u] = fmaf(c2, ta, fmaf(-cqa, kn2, Ca));
                sb[u] = fmaf(c2, tb, fmaf(-cqb, kn2, Cb));
            }
            // ---- phase 2: exp2 + PV accumulate (straight-line) ----
            #pragma unroll
            for (int u = 0; u < CH; u++) {
                float pa = ex2f(sa[u]);
                float pb = ex2f(sb[u]);
                ls0 += pa; ls1 += pb;
                u64 ppa = pk2(pa, pa), ppb = pk2(pb, pb);
                const ulonglong2* vp = (const ulonglong2*)&sV[(c0 + u) * 8];
                #pragma unroll
                for (int j = 0; j < 8; j++) {
                    ulonglong2 vv = vp[j];
                    acca[2*j]   = ffma2(ppa, vv.x, acca[2*j]);
                    acca[2*j+1] = ffma2(ppa, vv.y, acca[2*j+1]);
                    accb[2*j]   = ffma2(ppb, vv.x, accb[2*j]);
                    accb[2*j+1] = ffma2(ppb, vv.y, accb[2*j+1]);
                }
            }
        }
        __syncwarp();
    }

    // ---- write partials ----
    const int r0 = ((b * L_ + l0) * H_ + h);
    const int r1 = ((b * L_ + l1) * H_ + h);
    g_l[split * NR + r0] = ls0;
    g_l[split * NR + r1] = ls1;
    float4* pa4 = &g_acc[(size_t)(split * NR + r0) * 8];
    float4* pb4 = &g_acc[(size_t)(split * NR + r1) * 8];
    #pragma unroll
    for (int j = 0; j < 8; j++) {
        float2 x = upk2(acca[2*j]), y = upk2(acca[2*j+1]);
        pa4[j] = make_float4(x.x, x.y, y.x, y.y);
        float2 u = upk2(accb[2*j]), v = upk2(accb[2*j+1]);
        pb4[j] = make_float4(u.x, u.y, v.x, v.y);
    }

    // ---- last block of this group merges the splits (plain sums) ----
    const int g = blockIdx.x + (L_ / ROWSPB) * (h + H_ * b);
    __threadfence();
    int last = 0;
    if (tid == 0) {
        int prev = atomicAdd(&g_cnt[g], 1);
        last = (prev == SPLITS - 1);
    }
    last = __shfl_sync(0xffffffffu, last, 0);
    if (!last) return;
    __threadfence();

    // 32 threads merge 64 rows x 8 float4 chunks = 512 items.
    #pragma unroll 1
    for (int it = 0; it < (ROWSPB * 8) / THREADS; it++) {
        int item = it * THREADS + tid;
        int rl = item >> 3;
        int jj = item & 7;
        int r  = ((b * L_ + lbase + rl) * H_ + h);
        float denom = 0.f;
        float4 o = make_float4(0.f, 0.f, 0.f, 0.f);
        #pragma unroll
        for (int sp = 0; sp < SPLITS; sp++) {
            denom += g_l[sp * NR + r];
            float4 a = g_acc[(size_t)(sp * NR + r) * 8 + jj];
            o.x += a.x; o.y += a.y; o.z += a.z; o.w += a.w;
        }
        float inv = 1.0f / denom;
        o.x *= inv; o.y *= inv; o.z *= inv; o.w *= inv;
        ((float4*)O)[(size_t)r * 8 + jj] = o;
    }
    if (tid == 0) g_cnt[g] = 0;   // self-reset for next graph replay
}

extern "C" void kernel_launch(void* const* d_in, const int* in_sizes, int n_in,
                              void* d_out, int out_size) {
    const float* Q = (const float*)d_in[0];
    const float* K = (const float*)d_in[1];
    const float* V = (const float*)d_in[2];
    float* O = (float*)d_out;
    (void)in_sizes; (void)n_in; (void)out_size;
    kprep_kernel<<<B_ * H_, 256>>>(K);
    dim3 grid(L_ / ROWSPB, H_, B_ * SPLITS);   // 32 x 8 x 4 = 1024 blocks
    geom_attn_fused<<<grid, THREADS>>>(Q, K, V, O);
}

// round 13
// speedup vs baseline: 1.6483x; 1.6200x over previous
#include <cuda_runtime.h>
#include <cuda_bf16.h>
#include <math_constants.h>

// GeomAttention: B=2, L=S=2048, H=8, E=D=32, fp32.
// Cauchy-Schwarz => relu never fires: score = c*(dot+dot^2) - c*qn2*kn2.
// Shift softmax (log2): C2 = min(c2*qn2*KMIN, 100), p = 2^(score2 + C2).
//
// R13: R12 with the missing uint32_t type fixed (unsigned int). R9's exact
// geometry (64-thread blocks, 2 rows/thread, chunk-8, SPLITS=2) + cp.async
// double-buffered K/V tiles, split-wide kn2 preload, log2 ex2, packed fadd2
// dot reduce. Fused last-block merge unchanged.

static constexpr int B_ = 2, L_ = 2048, H_ = 8, E_ = 32;
static constexpr int SPLITS = 2;
static constexpr int SKEYS  = L_ / SPLITS;   // 1024
static constexpr int TS = 64;                // keys per SMEM tile
static constexpr int NT = SKEYS / TS;        // 16 tiles
static constexpr int CH = 8;                 // keys per score chunk
static constexpr int THREADS = 64;           // 2 warps
static constexpr int ROWSPB = 2 * THREADS;   // 128 rows per block
static constexpr int NR = B_ * L_ * H_;      // 32768 rows
static constexpr int NGROUPS = (L_ / ROWSPB) * H_ * B_;  // 256

__device__ float  g_l[SPLITS * NR];
__device__ float4 g_acc[SPLITS * NR * 8];
__device__ float  g_kmin[B_ * H_];
__device__ float  g_kn2[B_ * H_ * L_];       // [(b*H+h)*L + s]
__device__ int    g_cnt[NGROUPS];            // zero-init; self-resetting

typedef unsigned long long u64;
typedef unsigned int u32;

__device__ __forceinline__ u64 pk2(float a, float b) {
    u64 r; asm("mov.b64 %0, {%1,%2};" : "=l"(r) : "f"(a), "f"(b)); return r;
}
__device__ __forceinline__ float2 upk2(u64 v) {
    float2 r; asm("mov.b64 {%0,%1}, %2;" : "=f"(r.x), "=f"(r.y) : "l"(v)); return r;
}
__device__ __forceinline__ u64 ffma2(u64 a, u64 b, u64 c) {
    u64 d; asm("fma.rn.f32x2 %0, %1, %2, %3;" : "=l"(d) : "l"(a), "l"(b), "l"(c)); return d;
}
__device__ __forceinline__ u64 fadd2(u64 a, u64 b) {
    u64 d; asm("add.rn.f32x2 %0, %1, %2;" : "=l"(d) : "l"(a), "l"(b)); return d;
}
__device__ __forceinline__ float ex2f(float x) {
    float r; asm("ex2.approx.f32 %0, %1;" : "=f"(r) : "f"(x)); return r;
}
__device__ __forceinline__ u32 s2u(const void* p) {
    return (u32)__cvta_generic_to_shared(p);
}
__device__ __forceinline__ void cpa16(u32 dst, const void* src) {
    asm volatile("cp.async.cg.shared.global [%0], [%1], 16;" :: "r"(dst), "l"(src));
}
__device__ __forceinline__ void cpa4(u32 dst, const void* src) {
    asm volatile("cp.async.ca.shared.global [%0], [%1], 4;" :: "r"(dst), "l"(src));
}
#define CPA_COMMIT() asm volatile("cp.async.commit_group;" ::: "memory")
#define CPA_WAIT(n)  asm volatile("cp.async.wait_group %0;" :: "n"(n) : "memory")

// ---- pre-kernel: per-key |k|^2 and per-(b,h) min ----
__global__ __launch_bounds__(256) void kprep_kernel(const float* __restrict__ K)
{
    const int bh = blockIdx.x;               // 0..B*H-1
    const int b = bh / H_, h = bh % H_;
    const float* kbase = K + (((size_t)b * L_) * H_ + h) * E_;
    float mn = CUDART_INF_F;
    for (int s = threadIdx.x; s < L_; s += 256) {
        const float4* kp = (const float4*)(kbase + (size_t)s * (H_ * E_));
        float kn = 0.f;
        #pragma unroll
        for (int j = 0; j < 8; j++) {
            float4 v = kp[j];
            kn += v.x*v.x + v.y*v.y + v.z*v.z + v.w*v.w;
        }
        g_kn2[(size_t)bh * L_ + s] = kn;
        mn = fminf(mn, kn);
    }
    #pragma unroll
    for (int o = 16; o; o >>= 1) mn = fminf(mn, __shfl_xor_sync(0xffffffffu, mn, o));
    __shared__ float red[8];
    if ((threadIdx.x & 31) == 0) red[threadIdx.x >> 5] = mn;
    __syncthreads();
    if (threadIdx.x == 0) {
        float r = red[0];
        #pragma unroll
        for (int w = 1; w < 8; w++) r = fminf(r, red[w]);
        g_kmin[bh] = r;
    }
}

__global__ __launch_bounds__(THREADS, 4) void geom_attn_fused(
    const float* __restrict__ Q, const float* __restrict__ K,
    const float* __restrict__ V, float* __restrict__ O)
{
    __shared__ float4 sK[2][TS * 8];   // 2 x 8 KB
    __shared__ float4 sV[2][TS * 8];   // 2 x 8 KB
    __shared__ float  sKn2[SKEYS];     // 4 KB (whole split)
    __shared__ int    sLast;

    const int tid   = threadIdx.x;
    const int h     = blockIdx.y;
    const int bz    = blockIdx.z;
    const int b     = bz >> 1;                 // SPLITS == 2
    const int split = bz & 1;
    const int lbase = blockIdx.x * ROWSPB;
    const int l0    = lbase + tid;
    const int l1    = l0 + THREADS;
    const int bh    = b * H_ + h;

    const int key0 = split * SKEYS;
    const float* kbase = K + (((size_t)b * L_) * H_ + h) * E_;
    const float* vbase = V + (((size_t)b * L_) * H_ + h) * E_;
    const float* knb   = &g_kn2[(size_t)bh * L_ + key0];

    // ---- prologue: async-load kn2 for the whole split + tile 0 ----
    #pragma unroll
    for (int i = tid; i < SKEYS; i += THREADS)
        cpa4(s2u(&sKn2[i]), &knb[i]);
    #pragma unroll
    for (int i = tid; i < TS * 8; i += THREADS) {
        int r = i >> 3, j = i & 7;
        size_t off = (size_t)(key0 + r) * (H_ * E_) + j * 4;
        cpa16(s2u(&sK[0][i]), kbase + off);
        cpa16(s2u(&sV[0][i]), vbase + off);
    }
    CPA_COMMIT();

    // ---- load 2 query rows; |q|^2 each (overlaps with cp.async) ----
    const float* qp0 = Q + (((size_t)b * L_ + l0) * H_ + h) * E_;
    const float* qp1 = Q + (((size_t)b * L_ + l1) * H_ + h) * E_;
    u64 qa[16], qb[16];
    float qn2a = 0.f, qn2b = 0.f;
    #pragma unroll
    for (int j = 0; j < 8; j++) {
        float4 t = ((const float4*)qp0)[j];
        qa[2*j] = pk2(t.x, t.y); qa[2*j+1] = pk2(t.z, t.w);
        qn2a += t.x*t.x + t.y*t.y + t.z*t.z + t.w*t.w;
        float4 u = ((const float4*)qp1)[j];
        qb[2*j] = pk2(u.x, u.y); qb[2*j+1] = pk2(u.z, u.w);
        qn2b += u.x*u.x + u.y*u.y + u.z*u.z + u.w*u.w;
    }

    // log2-domain: p = 2^(c2*(dot+dot^2) - c2*qn2*kn2 + C2)
    const float c2  = 0.5f * rsqrtf((float)E_) * 1.4426950408889634f;
    const float cqa = c2 * qn2a, cqb = c2 * qn2b;
    const float km  = g_kmin[bh];
    const float Ca  = fminf(cqa * km, 100.f);  // safe fixed shift (log2)
    const float Cb  = fminf(cqb * km, 100.f);

    float ls0 = 0.f, ls1 = 0.f;
    u64 acca[16], accb[16];
    #pragma unroll
    for (int j = 0; j < 16; j++) { acca[j] = 0ull; accb[j] = 0ull; }

    for (int t = 0; t < NT; t++) {
        const int buf = t & 1;
        __syncthreads();                       // all warps done with buf^1
        if (t + 1 < NT) {                      // prefetch next tile
            #pragma unroll
            for (int i = tid; i < TS * 8; i += THREADS) {
                int r = i >> 3, j = i & 7;
                size_t off = (size_t)(key0 + (t + 1) * TS + r) * (H_ * E_) + j * 4;
                cpa16(s2u(&sK[buf ^ 1][i]), kbase + off);
                cpa16(s2u(&sV[buf ^ 1][i]), vbase + off);
            }
            CPA_COMMIT();
            CPA_WAIT(1);                       // tile t (older group) complete
        } else {
            CPA_WAIT(0);
        }
        __syncthreads();                       // cp.async data visible to all

        const int kofs = t * TS;
        for (int c0 = 0; c0 < TS; c0 += CH) {
            float sa[CH], sb[CH];
            // ---- phase 1: scores for CH keys x 2 rows ----
            #pragma unroll
            for (int u = 0; u < CH; u++) {
                const ulonglong2* kp = (const ulonglong2*)&sK[buf][(c0 + u) * 8];
                u64 a0 = 0ull, a1 = 0ull, b0 = 0ull, b1 = 0ull;
                #pragma unroll
                for (int j = 0; j < 8; j++) {
                    ulonglong2 kk = kp[j];          // broadcast across warp
                    a0 = ffma2(qa[2*j],   kk.x, a0);
                    a1 = ffma2(qa[2*j+1], kk.y, a1);
                    b0 = ffma2(qb[2*j],   kk.x, b0);
                    b1 = ffma2(qb[2*j+1], kk.y, b1);
                }
                float2 ra = upk2(fadd2(a0, a1));
                float2 rb = upk2(fadd2(b0, b1));
                float dota = ra.x + ra.y;
                float dotb = rb.x + rb.y;
                float kn2  = sKn2[kofs + c0 + u];
                float ta = fmaf(dota, dota, dota);   // dot + dot^2
                float tb = fmaf(dotb, dotb, dotb);
                sa[u] = fmaf(c2, ta, fmaf(-cqa, kn2, Ca));
                sb[u] = fmaf(c2, tb, fmaf(-cqb, kn2, Cb));
            }
            // ---- phase 2: exp2 + PV accumulate (straight-line) ----
            #pragma unroll
            for (int u = 0; u < CH; u++) {
                float pa = ex2f(sa[u]);
                float pb = ex2f(sb[u]);
                ls0 += pa; ls1 += pb;
                u64 ppa = pk2(pa, pa), ppb = pk2(pb, pb);
                const ulonglong2* vp = (const ulonglong2*)&sV[buf][(c0 + u) * 8];
                #pragma unroll
                for (int j = 0; j < 8; j++) {
                    ulonglong2 vv = vp[j];
                    acca[2*j]   = ffma2(ppa, vv.x, acca[2*j]);
                    acca[2*j+1] = ffma2(ppa, vv.y, acca[2*j+1]);
                    accb[2*j]   = ffma2(ppb, vv.x, accb[2*j]);
                    accb[2*j+1] = ffma2(ppb, vv.y, accb[2*j+1]);
                }
            }
        }
    }

    // ---- write partials ----
    const int r0 = ((b * L_ + l0) * H_ + h);
    const int r1 = ((b * L_ + l1) * H_ + h);
    g_l[split * NR + r0] = ls0;
    g_l[split * NR + r1] = ls1;
    float4* pa4 = &g_acc[(size_t)(split * NR + r0) * 8];
    float4* pb4 = &g_acc[(size_t)(split * NR + r1) * 8];
    #pragma unroll
    for (int j = 0; j < 8; j++) {
        float2 x = upk2(acca[2*j]), y = upk2(acca[2*j+1]);
        pa4[j] = make_float4(x.x, x.y, y.x, y.y);
        float2 u = upk2(accb[2*j]), v = upk2(accb[2*j+1]);
        pb4[j] = make_float4(u.x, u.y, v.x, v.y);
    }

    // ---- last block of this group merges the splits (plain sums) ----
    const int g = blockIdx.x + (L_ / ROWSPB) * (h + H_ * b);
    __threadfence();
    if (tid == 0) {
        int prev = atomicAdd(&g_cnt[g], 1);
        sLast = (prev == SPLITS - 1);
    }
    __syncthreads();
    if (!sLast) return;
    __threadfence();

    // 64 threads merge 128 rows x 8 float4 chunks = 1024 items.
    #pragma unroll 1
    for (int it = 0; it < (ROWSPB * 8) / THREADS; it++) {
        int item = it * THREADS + tid;
        int rl = item >> 3;
        int jj = item & 7;
        int r  = ((b * L_ + lbase + rl) * H_ + h);
        float denom = 0.f;
        float4 o = make_float4(0.f, 0.f, 0.f, 0.f);
        #pragma unroll
        for (int sp = 0; sp < SPLITS; sp++) {
            denom += g_l[sp * NR + r];
            float4 a = g_acc[(size_t)(sp * NR + r) * 8 + jj];
            o.x += a.x; o.y += a.y; o.z += a.z; o.w += a.w;
        }
        float inv = 1.0f / denom;
        o.x *= inv; o.y *= inv; o.z *= inv; o.w *= inv;
        ((float4*)O)[(size_t)r * 8 + jj] = o;
    }
    if (tid == 0) g_cnt[g] = 0;   // self-reset for next graph replay
}

extern "C" void kernel_launch(void* const* d_in, const int* in_sizes, int n_in,
                              void* d_out, int out_size) {
    const float* Q = (const float*)d_in[0];
    const float* K = (const float*)d_in[1];
    const float* V = (const float*)d_in[2];
    float* O = (float*)d_out;
    (void)in_sizes; (void)n_in; (void)out_size;
    kprep_kernel<<<B_ * H_, 256>>>(K);
    dim3 grid(L_ / ROWSPB, H_, B_ * SPLITS);   // 16 x 8 x 4 = 512 blocks
    geom_attn_fused<<<grid, THREADS>>>(Q, K, V, O);
}